// round 15
// baseline (speedup 1.0000x reference)
#include <cuda_runtime.h>
#include <cuda_fp16.h>
#include <math.h>
#include <stdint.h>

#define N_TOK 32768
#define DIM   768
#define HID   3072
#define NEXP  8
#define CAP   10240
#define MTILES (CAP / 128)          // 80
#define KCH1  (DIM / 64)            // 12
#define KCH2  (HID / 64)            // 48

// ---------------------------------------------------------------------------
// Scratch. Fragment-major fp16 blobs, 16KB each (1024 float4 units).
// ---------------------------------------------------------------------------
__device__ int    g_cnt[NEXP];
__device__ int    g_route_e[N_TOK * 2];
__device__ float  g_route_w[N_TOK * 2];
__device__ int    g_tokidx[NEXP * CAP];
__device__ int    g_slot[N_TOK * 2];
__device__ __half g_xg [(size_t)NEXP * CAP * DIM];
__device__ __half g_w1f[(size_t)NEXP * DIM * HID];
__device__ __half g_w2f[(size_t)NEXP * HID * DIM];
__device__ __half g_H  [(size_t)NEXP * CAP * HID];
__device__ float  g_Y  [(size_t)NEXP * CAP * DIM];

// ---------------------------------------------------------------------------
// Helpers
// ---------------------------------------------------------------------------
__device__ __forceinline__ void cp16s(uint32_t dst, const void* src) {
    asm volatile("cp.async.cg.shared.global [%0], [%1], 16;" :: "r"(dst), "l"(src));
}
#define CP_COMMIT() asm volatile("cp.async.commit_group;" ::: "memory")
#define CP_WAIT1()  asm volatile("cp.async.wait_group 1;" ::: "memory")

#define MMA_F16(c, a, b) \
    asm volatile("mma.sync.aligned.m16n8k16.row.col.f32.f16.f16.f32 " \
        "{%0,%1,%2,%3}, {%4,%5,%6,%7}, {%8,%9}, {%0,%1,%2,%3};" \
        : "+f"((c)[0]), "+f"((c)[1]), "+f"((c)[2]), "+f"((c)[3]) \
        : "r"((a)[0]), "r"((a)[1]), "r"((a)[2]), "r"((a)[3]), \
          "r"((b)[0]), "r"((b)[1]))

__device__ __forceinline__ float gelu_exact(float v) {
    return 0.5f * v * (1.f + erff(v * 0.70710678118654752f));
}

// ---------------------------------------------------------------------------
// Kernel 0: PREP = zero counters + router + both weight->blob transforms.
// ---------------------------------------------------------------------------
__global__ __launch_bounds__(256) void prep_kernel(
    const float* __restrict__ x,  const float* __restrict__ wg,
    const float* __restrict__ w1, const float* __restrict__ w2)
{
    __shared__ float tile[64][132];
    const int b = blockIdx.x;
    const int tid = threadIdx.x;

    if (b < 4096) {
        if (b == 0 && tid < NEXP) g_cnt[tid] = 0;
        int warp = b * 8 + (tid >> 5);
        int lane = tid & 31;
        const float* xr = x + (size_t)warp * DIM;

        float acc[NEXP];
#pragma unroll
        for (int e = 0; e < NEXP; e++) acc[e] = 0.f;
        for (int j = lane; j < DIM; j += 32) {
            float xv = xr[j];
            const float* wr = wg + j * NEXP;
#pragma unroll
            for (int e = 0; e < NEXP; e++) acc[e] += xv * wr[e];
        }
#pragma unroll
        for (int e = 0; e < NEXP; e++) {
#pragma unroll
            for (int o = 16; o > 0; o >>= 1)
                acc[e] += __shfl_xor_sync(0xffffffffu, acc[e], o);
        }
        if (lane == 0) {
            int e0 = 0; float v0 = acc[0];
#pragma unroll
            for (int e = 1; e < NEXP; e++) if (acc[e] > v0) { v0 = acc[e]; e0 = e; }
            int e1 = -1; float v1 = -3.4e38f;
#pragma unroll
            for (int e = 0; e < NEXP; e++) if (e != e0 && acc[e] > v1) { v1 = acc[e]; e1 = e; }
            float ex = expf(v1 - v0);
            float s  = 1.f + ex;
            g_route_e[2 * warp + 0] = e0;  g_route_w[2 * warp + 0] = 1.f / s;
            g_route_e[2 * warp + 1] = e1;  g_route_w[2 * warp + 1] = ex / s;
        }
        return;
    }

    int wb = b - 4096;
    const float* w;
    __half* out;
    int KD, nkc;
    size_t ndiv;
    if (wb < 2304) { w = w1; out = g_w1f; KD = DIM; nkc = 12; ndiv = HID / 128; }
    else           { wb -= 2304; w = w2; out = g_w2f; KD = HID; nkc = 48; ndiv = DIM / 128; }
    const int ND = (int)(ndiv * 128);
    const int e  = wb / 288;
    const int r  = wb % 288;
    const int nt = r / nkc;
    const int kc = r % nkc;

    const float* src = w + ((size_t)e * KD + kc * 64) * ND + nt * 128;
#pragma unroll
    for (int u = tid; u < 2048; u += 256) {
        int rr = u >> 5, c = (u & 31) * 4;
        float4 v = *(const float4*)(src + (size_t)rr * ND + c);
        tile[rr][c + 0] = v.x; tile[rr][c + 1] = v.y;
        tile[rr][c + 2] = v.z; tile[rr][c + 3] = v.w;
    }
    __syncthreads();

    float4* dst = (float4*)(out + (((size_t)(e * ndiv + nt) * nkc + kc) << 13));
#pragma unroll
    for (int u = tid; u < 1024; u += 256) {
        int t = u & 31, pp = (u >> 5) & 7, ks = u >> 8;
        int gid = t >> 2, tig = t & 3;
        __half2 h[4];
#pragma unroll
        for (int j = 0; j < 4; j++) {
            int n = pp * 16 + 8 * (j >> 1) + gid;
            int k = ks * 16 + tig * 2 + 8 * (j & 1);
            h[j] = __floats2half2_rn(tile[k][n], tile[k + 1][n]);
        }
        float4 v;
        v.x = __uint_as_float(*(uint32_t*)&h[0]);
        v.y = __uint_as_float(*(uint32_t*)&h[1]);
        v.z = __uint_as_float(*(uint32_t*)&h[2]);
        v.w = __uint_as_float(*(uint32_t*)&h[3]);
        dst[u] = v;
    }
}

// ---------------------------------------------------------------------------
// Kernel 1: slot assignment
// ---------------------------------------------------------------------------
__global__ void assign_kernel() {
    int t = blockIdx.x * blockDim.x + threadIdx.x;
    if (t >= N_TOK) return;
#pragma unroll
    for (int k = 0; k < 2; k++) {
        int e = g_route_e[2 * t + k];
        int pos = atomicAdd(&g_cnt[e], 1);
        if (pos < CAP) {
            g_tokidx[e * CAP + pos] = t;
            g_slot[2 * t + k] = e * CAP + pos;
        } else {
            g_slot[2 * t + k] = -1;
        }
    }
}

// ---------------------------------------------------------------------------
// Kernel 2: gather routed tokens into fp16 A-blobs
// ---------------------------------------------------------------------------
__global__ __launch_bounds__(256) void gather_frag_kernel(const float* __restrict__ x) {
    const int e = blockIdx.y;
    const int Me = min(g_cnt[e], CAP);
    const int g16 = blockIdx.x;
    const int base = g16 * 16;
    if (base >= Me) return;

    __shared__ float rows[16][772];
    const int tid = threadIdx.x;

    for (int u = tid; u < 16 * 192; u += 256) {
        int r = u / 192, c = (u % 192) * 4;
        int pos = base + r;
        if (pos < Me) {
            int tok = g_tokidx[e * CAP + pos];
            float4 v = *(const float4*)(x + (size_t)tok * DIM + c);
            rows[r][c + 0] = v.x; rows[r][c + 1] = v.y;
            rows[r][c + 2] = v.z; rows[r][c + 3] = v.w;
        } else {
            rows[r][c + 0] = 0.f; rows[r][c + 1] = 0.f;
            rows[r][c + 2] = 0.f; rows[r][c + 3] = 0.f;
        }
    }
    __syncthreads();

    const int mtile = g16 >> 3, m16blk = g16 & 7;
    float4* outb = (float4*)g_xg;
    for (int u = tid; u < 1536; u += 256) {
        int kc = u >> 7, r = u & 127;
        int ks = r >> 5, t = r & 31;
        int gid = t >> 2, tig = t & 3;
        __half2 h[4];
#pragma unroll
        for (int j = 0; j < 4; j++) {
            int row = gid + 8 * (j & 1);
            int col = kc * 64 + ks * 16 + tig * 2 + 8 * (j >> 1);
            h[j] = __floats2half2_rn(rows[row][col], rows[row][col + 1]);
        }
        float4 v;
        v.x = __uint_as_float(*(uint32_t*)&h[0]);
        v.y = __uint_as_float(*(uint32_t*)&h[1]);
        v.z = __uint_as_float(*(uint32_t*)&h[2]);
        v.w = __uint_as_float(*(uint32_t*)&h[3]);
        outb[(((size_t)((e * MTILES + mtile) * KCH1 + kc)) << 10) + m16blk * 128 + ks * 32 + t] = v;
    }
}

// ---------------------------------------------------------------------------
// fp16 fragment-major GEMM. CTA 128x128, 8 warps (4x2), warp tile 32x64.
//   256 threads, acc[2][8][4]=64 regs -> 2 CTAs/SM = 4 warps/SMSP for stall
//   filling. R13 strength-reduced mainloop + R14 folded epilogue, re-derived
//   for the 8-warp geometry.
// ---------------------------------------------------------------------------
template<int NKCH, int NDIM, bool EPI_FRAG>
__global__ __launch_bounds__(256, 2) void gemm_f16_kernel(
    const __half* __restrict__ Ablobs,
    const __half* __restrict__ Bblobs,
    const float* __restrict__ bias,
    void* __restrict__ Cout)
{
    static_assert(NKCH % 3 == 0, "stage ring requires NKCH % 3 == 0");
    const int e  = blockIdx.z;
    const int Me = min(g_cnt[e], CAP);
    const int m0 = blockIdx.y * 128;
    if (m0 >= Me) return;
    const int bx = blockIdx.x;

    extern __shared__ float smem[];           // 3 stages x 8192 floats (32KB)
    const int tid = threadIdx.x;
    const int wid = tid >> 5, lid = tid & 31;
    const int gid = lid >> 2, tig = lid & 3;
    const int wMblk = (wid >> 1) * 2;         // m16 block base (0,2,4,6)
    const int pbase = (wid & 1) * 4;          // B pair base (0 or 4)

    const float4* Ab = (const float4*)(Ablobs + (((size_t)(e * MTILES + blockIdx.y) * NKCH) << 13));
    const float4* Bb = (const float4*)(Bblobs + (((size_t)(e * (NDIM / 128) + bx) * NKCH) << 13));

    uint32_t cpd;
    asm("{ .reg .u64 t; cvta.to.shared.u64 t, %1; cvt.u32.u64 %0, t; }"
        : "=r"(cpd) : "l"(smem));
    cpd += tid * 16;

    const float4* fA = (const float4*)smem + wMblk * 128 + lid;
    const float4* fB = (const float4*)smem + 1024 + pbase * 32 + lid;

    float acc[2][8][4];
#pragma unroll
    for (int mf = 0; mf < 2; mf++)
#pragma unroll
        for (int nf = 0; nf < 8; nf++)
#pragma unroll
            for (int q = 0; q < 4; q++) acc[mf][nf][q] = 0.f;

    // prologue: full issue of chunks 0 and 1 (8 f4 per thread per chunk)
    {
        const float4* a0 = Ab + tid;
        const float4* b0 = Bb + tid;
#pragma unroll
        for (int s = 0; s < 2; s++) {
#pragma unroll
            for (int j = 0; j < 4; j++)
                cp16s(cpd + s * 32768 + j * 4096, a0 + s * 1024 + j * 256);
#pragma unroll
            for (int j = 0; j < 4; j++)
                cp16s(cpd + s * 32768 + 16384 + j * 4096, b0 + s * 1024 + j * 256);
            CP_COMMIT();
        }
    }

    const float4* gpa = Ab + 2048 + tid;
    const float4* gpb = Bb + 2048 + tid;

#define GEMM_BODY(ICHUNK, S_CUR, S_PF)                                         \
    {                                                                          \
        const bool pf = ((ICHUNK) + 2 < NKCH);                                 \
        CP_WAIT1();                                                            \
        __syncthreads();                                                       \
        _Pragma("unroll")                                                      \
        for (int ks = 0; ks < 4; ks++) {                                       \
            uint32_t a[2][4], b[8][2];                                         \
            _Pragma("unroll")                                                  \
            for (int mf = 0; mf < 2; mf++) {                                   \
                float4 v = fA[(S_CUR) * 2048 + mf * 128 + ks * 32];            \
                a[mf][0] = __float_as_uint(v.x);                               \
                a[mf][1] = __float_as_uint(v.y);                               \
                a[mf][2] = __float_as_uint(v.z);                               \
                a[mf][3] = __float_as_uint(v.w);                               \
            }                                                                  \
            _Pragma("unroll")                                                  \
            for (int q = 0; q < 4; q++) {                                      \
                float4 v = fB[(S_CUR) * 2048 + ks * 256 + q * 32];             \
                b[2 * q + 0][0] = __float_as_uint(v.x);                        \
                b[2 * q + 0][1] = __float_as_uint(v.y);                        \
                b[2 * q + 1][0] = __float_as_uint(v.z);                        \
                b[2 * q + 1][1] = __float_as_uint(v.w);                        \
            }                                                                  \
            if (pf) {                                                          \
                _Pragma("unroll")                                              \
                for (int jj = 0; jj < 2; jj++) {                               \
                    int j = ks * 2 + jj;                                       \
                    if (j < 4) cp16s(cpd + (S_PF) * 32768 + j * 4096,          \
                                     gpa + j * 256);                           \
                    else       cp16s(cpd + (S_PF) * 32768 + 16384 + (j - 4) * 4096, \
                                     gpb + (j - 4) * 256);                     \
                }                                                              \
            }                                                                  \
            _Pragma("unroll")                                                  \
            for (int mf = 0; mf < 2; mf++)                                     \
                _Pragma("unroll")                                              \
                for (int nf = 0; nf < 8; nf++)                                 \
                    MMA_F16(acc[mf][nf], a[mf], b[nf]);                        \
        }                                                                      \
        CP_COMMIT();                                                           \
        gpa += 1024; gpb += 1024;                                              \
    }

    for (int i = 0; i < NKCH; i += 3) {
        GEMM_BODY(i,     0, 2)
        GEMM_BODY(i + 1, 1, 0)
        GEMM_BODY(i + 2, 2, 1)
    }
#undef GEMM_BODY

    const int warpM = (wid >> 1) * 32;        // 0,32,64,96
    const int warpN = (wid & 1) * 64;         // 0 or 64
    const int n0 = bx * 128;
    const float* bp = bias + (size_t)e * NDIM + n0 + warpN;

    float2 br[8];
#pragma unroll
    for (int nf = 0; nf < 8; nf++)
        br[nf] = *(const float2*)(bp + nf * 8 + tig * 2);

    if (EPI_FRAG) {
        __syncthreads();
        // Folded H-blob addressing (8-warp geometry):
        //   m16blk = (wid>>1)*2 + mf ; kc_l = wid&1 ; ks = nf>>1 ; t_a = lid
        const int tw = lid ^ (((lid >> 3) & 3) << 1);
        __half2* sh = (__half2*)smem + (wid & 1) * 4096 + (wid >> 1) * 1024 + tw * 4;
#pragma unroll
        for (int mf = 0; mf < 2; mf++) {
#pragma unroll
            for (int nf = 0; nf < 8; nf++) {
                float v0 = gelu_exact(acc[mf][nf][0] + br[nf].x);
                float v1 = gelu_exact(acc[mf][nf][1] + br[nf].y);
                float v2 = gelu_exact(acc[mf][nf][2] + br[nf].x);
                float v3 = gelu_exact(acc[mf][nf][3] + br[nf].y);
                __half2 h0 = __floats2half2_rn(v0, v1);   // half = 0
                __half2 h1 = __floats2half2_rn(v2, v3);   // half = 1
                uint2 u;
                u.x = *(uint32_t*)&h0;
                u.y = *(uint32_t*)&h1;
                *(uint2*)(sh + mf * 512 + (nf >> 1) * 128 + 2 * (nf & 1)) = u;
            }
        }
        __syncthreads();
        float4* dst = (float4*)((__half*)Cout +
            (((size_t)((e * MTILES + blockIdx.y) * KCH2 + bx * 2)) << 13));
        const float4* st = (const float4*)smem;
#pragma unroll
        for (int u = tid; u < 2048; u += 256) {
            int t = u & 31;
            int twc = t ^ (((t >> 3) & 3) << 1);
            dst[u] = st[(u & ~31) | twc];
        }
    } else {
        float* Cf = (float*)Cout;
#pragma unroll
        for (int mf = 0; mf < 2; mf++)
#pragma unroll
            for (int half = 0; half < 2; half++) {
                int m = m0 + warpM + mf * 16 + gid + half * 8;
                if (m >= Me) continue;
                float* Crow = Cf + (size_t)(e * CAP + m) * NDIM + n0 + warpN + tig * 2;
#pragma unroll
                for (int nf = 0; nf < 8; nf++) {
                    float2 o;
                    o.x = acc[mf][nf][half * 2 + 0] + br[nf].x;
                    o.y = acc[mf][nf][half * 2 + 1] + br[nf].y;
                    *(float2*)(Crow + nf * 8) = o;
                }
            }
    }
}

// ---------------------------------------------------------------------------
// combine + LayerNorm
// ---------------------------------------------------------------------------
__global__ __launch_bounds__(256) void combine_ln_kernel(
    const float* __restrict__ lnw,
    const float* __restrict__ lnb,
    float* __restrict__ out)
{
    const int t   = blockIdx.x;
    const int tid = threadIdx.x;
    const int s0  = g_slot[2 * t + 0];
    const int s1  = g_slot[2 * t + 1];
    const float w0 = g_route_w[2 * t + 0];
    const float w1 = g_route_w[2 * t + 1];

    float v[3];
    float sum = 0.f;
#pragma unroll
    for (int r = 0; r < 3; r++) {
        int i = r * 256 + tid;
        float a = (s0 >= 0) ? g_Y[(size_t)s0 * DIM + i] : 0.f;
        float b = (s1 >= 0) ? g_Y[(size_t)s1 * DIM + i] : 0.f;
        v[r] = w0 * a + w1 * b;
        sum += v[r];
    }

    __shared__ float red[256];
    red[tid] = sum;
    __syncthreads();
#pragma unroll
    for (int o = 128; o > 0; o >>= 1) {
        if (tid < o) red[tid] += red[tid + o];
        __syncthreads();
    }
    float mu = red[0] * (1.f / (float)DIM);
    __syncthreads();

    float sq = 0.f;
#pragma unroll
    for (int r = 0; r < 3; r++) { float d = v[r] - mu; sq += d * d; }
    red[tid] = sq;
    __syncthreads();
#pragma unroll
    for (int o = 128; o > 0; o >>= 1) {
        if (tid < o) red[tid] += red[tid + o];
        __syncthreads();
    }
    float rstd = rsqrtf(red[0] * (1.f / (float)DIM) + 1e-5f);

#pragma unroll
    for (int r = 0; r < 3; r++) {
        int i = r * 256 + tid;
        out[(size_t)t * DIM + i] = (v[r] - mu) * rstd * lnw[i] + lnb[i];
    }
}

// ---------------------------------------------------------------------------
// Launch:  prep(0), assign(1), gather(2), gemm1(3), gemm2(4), combine(5)
// ---------------------------------------------------------------------------
extern "C" void kernel_launch(void* const* d_in, const int* in_sizes, int n_in,
                              void* d_out, int out_size)
{
    const float* x   = (const float*)d_in[0];
    const float* wg  = (const float*)d_in[1];
    const float* w1  = (const float*)d_in[2];
    const float* b1  = (const float*)d_in[3];
    const float* w2  = (const float*)d_in[4];
    const float* b2  = (const float*)d_in[5];
    const float* lnw = (const float*)d_in[6];
    const float* lnb = (const float*)d_in[7];
    float* out = (float*)d_out;

    const int SMEM_BYTES = 3 * 8192 * 4;   // 98304
    cudaFuncSetAttribute(gemm_f16_kernel<KCH1, HID, true>,
                         cudaFuncAttributeMaxDynamicSharedMemorySize, SMEM_BYTES);
    cudaFuncSetAttribute(gemm_f16_kernel<KCH2, DIM, false>,
                         cudaFuncAttributeMaxDynamicSharedMemorySize, SMEM_BYTES);

    __half* w1f; cudaGetSymbolAddress((void**)&w1f, g_w1f);
    __half* w2f; cudaGetSymbolAddress((void**)&w2f, g_w2f);
    __half* xg;  cudaGetSymbolAddress((void**)&xg,  g_xg);
    __half* Hbuf; cudaGetSymbolAddress((void**)&Hbuf, g_H);
    float* Ybuf; cudaGetSymbolAddress((void**)&Ybuf, g_Y);

    prep_kernel<<<4096 + 4608, 256>>>(x, wg, w1, w2);
    assign_kernel<<<N_TOK / 256, 256>>>();
    gather_frag_kernel<<<dim3(CAP / 16, NEXP), 256>>>(x);

    gemm_f16_kernel<KCH1, HID, true><<<dim3(HID / 128, MTILES, NEXP), 256, SMEM_BYTES>>>(
        xg, w1f, b1, Hbuf);
    gemm_f16_kernel<KCH2, DIM, false><<<dim3(DIM / 128, MTILES, NEXP), 256, SMEM_BYTES>>>(
        Hbuf, w2f, b2, Ybuf);

    combine_ln_kernel<<<N_TOK, 256>>>(lnw, lnb, out);
}

// round 16
// speedup vs baseline: 1.0494x; 1.0494x over previous
#include <cuda_runtime.h>
#include <cuda_fp16.h>
#include <math.h>
#include <stdint.h>

#define N_TOK 32768
#define DIM   768
#define HID   3072
#define NEXP  8
#define CAP   10240
#define MTILES (CAP / 128)          // 80
#define KCH1  (DIM / 64)            // 12
#define KCH2  (HID / 64)            // 48

// ---------------------------------------------------------------------------
// Scratch. Fragment-major fp16 blobs, 16KB each (1024 float4 units).
// ---------------------------------------------------------------------------
__device__ int    g_cnt[NEXP];
__device__ int    g_route_e[N_TOK * 2];
__device__ float  g_route_w[N_TOK * 2];
__device__ int    g_tokidx[NEXP * CAP];
__device__ int    g_slot[N_TOK * 2];
__device__ __half g_xg [(size_t)NEXP * CAP * DIM];
__device__ __half g_w1f[(size_t)NEXP * DIM * HID];
__device__ __half g_w2f[(size_t)NEXP * HID * DIM];
__device__ __half g_H  [(size_t)NEXP * CAP * HID];
__device__ float  g_Y  [(size_t)NEXP * CAP * DIM];

// ---------------------------------------------------------------------------
// Helpers
// ---------------------------------------------------------------------------
__device__ __forceinline__ void cp16s(uint32_t dst, const void* src) {
    asm volatile("cp.async.cg.shared.global [%0], [%1], 16;" :: "r"(dst), "l"(src));
}
#define CP_COMMIT() asm volatile("cp.async.commit_group;" ::: "memory")
#define CP_WAIT1()  asm volatile("cp.async.wait_group 1;" ::: "memory")

#define MMA_F16(c, a, b) \
    asm volatile("mma.sync.aligned.m16n8k16.row.col.f32.f16.f16.f32 " \
        "{%0,%1,%2,%3}, {%4,%5,%6,%7}, {%8,%9}, {%0,%1,%2,%3};" \
        : "+f"((c)[0]), "+f"((c)[1]), "+f"((c)[2]), "+f"((c)[3]) \
        : "r"((a)[0]), "r"((a)[1]), "r"((a)[2]), "r"((a)[3]), \
          "r"((b)[0]), "r"((b)[1]))

__device__ __forceinline__ float gelu_exact(float v) {
    return 0.5f * v * (1.f + erff(v * 0.70710678118654752f));
}

// ---------------------------------------------------------------------------
// Kernel 0: PREP = zero counters + router + both weight->blob transforms.
// ---------------------------------------------------------------------------
__global__ __launch_bounds__(256) void prep_kernel(
    const float* __restrict__ x,  const float* __restrict__ wg,
    const float* __restrict__ w1, const float* __restrict__ w2)
{
    __shared__ float tile[64][132];
    const int b = blockIdx.x;
    const int tid = threadIdx.x;

    if (b < 4096) {
        if (b == 0 && tid < NEXP) g_cnt[tid] = 0;
        int warp = b * 8 + (tid >> 5);
        int lane = tid & 31;
        const float* xr = x + (size_t)warp * DIM;

        float acc[NEXP];
#pragma unroll
        for (int e = 0; e < NEXP; e++) acc[e] = 0.f;
        for (int j = lane; j < DIM; j += 32) {
            float xv = xr[j];
            const float* wr = wg + j * NEXP;
#pragma unroll
            for (int e = 0; e < NEXP; e++) acc[e] += xv * wr[e];
        }
#pragma unroll
        for (int e = 0; e < NEXP; e++) {
#pragma unroll
            for (int o = 16; o > 0; o >>= 1)
                acc[e] += __shfl_xor_sync(0xffffffffu, acc[e], o);
        }
        if (lane == 0) {
            int e0 = 0; float v0 = acc[0];
#pragma unroll
            for (int e = 1; e < NEXP; e++) if (acc[e] > v0) { v0 = acc[e]; e0 = e; }
            int e1 = -1; float v1 = -3.4e38f;
#pragma unroll
            for (int e = 0; e < NEXP; e++) if (e != e0 && acc[e] > v1) { v1 = acc[e]; e1 = e; }
            float ex = expf(v1 - v0);
            float s  = 1.f + ex;
            g_route_e[2 * warp + 0] = e0;  g_route_w[2 * warp + 0] = 1.f / s;
            g_route_e[2 * warp + 1] = e1;  g_route_w[2 * warp + 1] = ex / s;
        }
        return;
    }

    int wb = b - 4096;
    const float* w;
    __half* out;
    int KD, nkc;
    size_t ndiv;
    if (wb < 2304) { w = w1; out = g_w1f; KD = DIM; nkc = 12; ndiv = HID / 128; }
    else           { wb -= 2304; w = w2; out = g_w2f; KD = HID; nkc = 48; ndiv = DIM / 128; }
    const int ND = (int)(ndiv * 128);
    const int e  = wb / 288;
    const int r  = wb % 288;
    const int nt = r / nkc;
    const int kc = r % nkc;

    const float* src = w + ((size_t)e * KD + kc * 64) * ND + nt * 128;
#pragma unroll
    for (int u = tid; u < 2048; u += 256) {
        int rr = u >> 5, c = (u & 31) * 4;
        float4 v = *(const float4*)(src + (size_t)rr * ND + c);
        tile[rr][c + 0] = v.x; tile[rr][c + 1] = v.y;
        tile[rr][c + 2] = v.z; tile[rr][c + 3] = v.w;
    }
    __syncthreads();

    float4* dst = (float4*)(out + (((size_t)(e * ndiv + nt) * nkc + kc) << 13));
#pragma unroll
    for (int u = tid; u < 1024; u += 256) {
        int t = u & 31, pp = (u >> 5) & 7, ks = u >> 8;
        int gid = t >> 2, tig = t & 3;
        __half2 h[4];
#pragma unroll
        for (int j = 0; j < 4; j++) {
            int n = pp * 16 + 8 * (j >> 1) + gid;
            int k = ks * 16 + tig * 2 + 8 * (j & 1);
            h[j] = __floats2half2_rn(tile[k][n], tile[k + 1][n]);
        }
        float4 v;
        v.x = __uint_as_float(*(uint32_t*)&h[0]);
        v.y = __uint_as_float(*(uint32_t*)&h[1]);
        v.z = __uint_as_float(*(uint32_t*)&h[2]);
        v.w = __uint_as_float(*(uint32_t*)&h[3]);
        dst[u] = v;
    }
}

// ---------------------------------------------------------------------------
// Kernel 1: slot assignment
// ---------------------------------------------------------------------------
__global__ void assign_kernel() {
    int t = blockIdx.x * blockDim.x + threadIdx.x;
    if (t >= N_TOK) return;
#pragma unroll
    for (int k = 0; k < 2; k++) {
        int e = g_route_e[2 * t + k];
        int pos = atomicAdd(&g_cnt[e], 1);
        if (pos < CAP) {
            g_tokidx[e * CAP + pos] = t;
            g_slot[2 * t + k] = e * CAP + pos;
        } else {
            g_slot[2 * t + k] = -1;
        }
    }
}

// ---------------------------------------------------------------------------
// Kernel 2: gather routed tokens into fp16 A-blobs
// ---------------------------------------------------------------------------
__global__ __launch_bounds__(256) void gather_frag_kernel(const float* __restrict__ x) {
    const int e = blockIdx.y;
    const int Me = min(g_cnt[e], CAP);
    const int g16 = blockIdx.x;
    const int base = g16 * 16;
    if (base >= Me) return;

    __shared__ float rows[16][772];
    const int tid = threadIdx.x;

    for (int u = tid; u < 16 * 192; u += 256) {
        int r = u / 192, c = (u % 192) * 4;
        int pos = base + r;
        if (pos < Me) {
            int tok = g_tokidx[e * CAP + pos];
            float4 v = *(const float4*)(x + (size_t)tok * DIM + c);
            rows[r][c + 0] = v.x; rows[r][c + 1] = v.y;
            rows[r][c + 2] = v.z; rows[r][c + 3] = v.w;
        } else {
            rows[r][c + 0] = 0.f; rows[r][c + 1] = 0.f;
            rows[r][c + 2] = 0.f; rows[r][c + 3] = 0.f;
        }
    }
    __syncthreads();

    const int mtile = g16 >> 3, m16blk = g16 & 7;
    float4* outb = (float4*)g_xg;
    for (int u = tid; u < 1536; u += 256) {
        int kc = u >> 7, r = u & 127;
        int ks = r >> 5, t = r & 31;
        int gid = t >> 2, tig = t & 3;
        __half2 h[4];
#pragma unroll
        for (int j = 0; j < 4; j++) {
            int row = gid + 8 * (j & 1);
            int col = kc * 64 + ks * 16 + tig * 2 + 8 * (j >> 1);
            h[j] = __floats2half2_rn(rows[row][col], rows[row][col + 1]);
        }
        float4 v;
        v.x = __uint_as_float(*(uint32_t*)&h[0]);
        v.y = __uint_as_float(*(uint32_t*)&h[1]);
        v.z = __uint_as_float(*(uint32_t*)&h[2]);
        v.w = __uint_as_float(*(uint32_t*)&h[3]);
        outb[(((size_t)((e * MTILES + mtile) * KCH1 + kc)) << 10) + m16blk * 128 + ks * 32 + t] = v;
    }
}

// ---------------------------------------------------------------------------
// fp16 fragment-major GEMM. CTA 128x128, 4 warps (2x2), warp tile 64x64
//   (the R14 configuration) + intra-chunk fragment double-buffering:
//   LDS for ks+1 issue before MMAs of ks, hiding smem latency in-warp.
// ---------------------------------------------------------------------------
template<int NKCH, int NDIM, bool EPI_FRAG>
__global__ __launch_bounds__(128, 2) void gemm_f16_kernel(
    const __half* __restrict__ Ablobs,
    const __half* __restrict__ Bblobs,
    const float* __restrict__ bias,
    void* __restrict__ Cout)
{
    static_assert(NKCH % 3 == 0, "stage ring requires NKCH % 3 == 0");
    const int e  = blockIdx.z;
    const int Me = min(g_cnt[e], CAP);
    const int m0 = blockIdx.y * 128;
    if (m0 >= Me) return;
    const int bx = blockIdx.x;

    extern __shared__ float smem[];           // 3 stages x 8192 floats (32KB)
    const int tid = threadIdx.x;
    const int wid = tid >> 5, lid = tid & 31;
    const int gid = lid >> 2, tig = lid & 3;
    const int wMblk = (wid >> 1) * 4;
    const int pbase = (wid & 1) * 4;

    const float4* Ab = (const float4*)(Ablobs + (((size_t)(e * MTILES + blockIdx.y) * NKCH) << 13));
    const float4* Bb = (const float4*)(Bblobs + (((size_t)(e * (NDIM / 128) + bx) * NKCH) << 13));

    uint32_t cpd;
    asm("{ .reg .u64 t; cvta.to.shared.u64 t, %1; cvt.u32.u64 %0, t; }"
        : "=r"(cpd) : "l"(smem));
    cpd += tid * 16;

    const float4* fA = (const float4*)smem + wMblk * 128 + lid;
    const float4* fB = (const float4*)smem + 1024 + pbase * 32 + lid;

    float acc[4][8][4];
#pragma unroll
    for (int mf = 0; mf < 4; mf++)
#pragma unroll
        for (int nf = 0; nf < 8; nf++)
#pragma unroll
            for (int q = 0; q < 4; q++) acc[mf][nf][q] = 0.f;

    // prologue: full issue of chunks 0 and 1 (16 f4 per thread per chunk)
    {
        const float4* a0 = Ab + tid;
        const float4* b0 = Bb + tid;
#pragma unroll
        for (int s = 0; s < 2; s++) {
#pragma unroll
            for (int j = 0; j < 8; j++)
                cp16s(cpd + s * 32768 + j * 2048, a0 + s * 1024 + j * 128);
#pragma unroll
            for (int j = 0; j < 8; j++)
                cp16s(cpd + s * 32768 + 16384 + j * 2048, b0 + s * 1024 + j * 128);
            CP_COMMIT();
        }
    }

    const float4* gpa = Ab + 2048 + tid;
    const float4* gpb = Bb + 2048 + tid;

    // double-buffered fragment registers
    uint32_t a[2][4][4], b[2][8][2];

#define LOADFRAG(S_CUR, KS, BUF)                                               \
    {                                                                          \
        _Pragma("unroll")                                                      \
        for (int mf = 0; mf < 4; mf++) {                                       \
            float4 v = fA[(S_CUR) * 2048 + mf * 128 + (KS) * 32];              \
            a[BUF][mf][0] = __float_as_uint(v.x);                              \
            a[BUF][mf][1] = __float_as_uint(v.y);                              \
            a[BUF][mf][2] = __float_as_uint(v.z);                              \
            a[BUF][mf][3] = __float_as_uint(v.w);                              \
        }                                                                      \
        _Pragma("unroll")                                                      \
        for (int q = 0; q < 4; q++) {                                          \
            float4 v = fB[(S_CUR) * 2048 + (KS) * 256 + q * 32];               \
            b[BUF][2 * q + 0][0] = __float_as_uint(v.x);                       \
            b[BUF][2 * q + 0][1] = __float_as_uint(v.y);                       \
            b[BUF][2 * q + 1][0] = __float_as_uint(v.z);                       \
            b[BUF][2 * q + 1][1] = __float_as_uint(v.w);                       \
        }                                                                      \
    }

#define PF(KS, S_PF)                                                           \
    if (pf) {                                                                  \
        _Pragma("unroll")                                                      \
        for (int jj = 0; jj < 4; jj++) {                                       \
            int j = (KS) * 4 + jj;                                             \
            if (j < 8) cp16s(cpd + (S_PF) * 32768 + j * 2048, gpa + j * 128);  \
            else       cp16s(cpd + (S_PF) * 32768 + 16384 + (j - 8) * 2048,    \
                             gpb + (j - 8) * 128);                             \
        }                                                                      \
    }

#define MMAS(BUF)                                                              \
    _Pragma("unroll")                                                          \
    for (int mf = 0; mf < 4; mf++)                                             \
        _Pragma("unroll")                                                      \
        for (int nf = 0; nf < 8; nf++)                                         \
            MMA_F16(acc[mf][nf], a[BUF][mf], b[BUF][nf]);

#define GEMM_BODY(ICHUNK, S_CUR, S_PF)                                         \
    {                                                                          \
        const bool pf = ((ICHUNK) + 2 < NKCH);                                 \
        CP_WAIT1();                                                            \
        __syncthreads();                                                       \
        LOADFRAG(S_CUR, 0, 0)                                                  \
        LOADFRAG(S_CUR, 1, 1) PF(0, S_PF) MMAS(0)                              \
        LOADFRAG(S_CUR, 2, 0) PF(1, S_PF) MMAS(1)                              \
        LOADFRAG(S_CUR, 3, 1) PF(2, S_PF) MMAS(0)                              \
                              PF(3, S_PF) MMAS(1)                              \
        CP_COMMIT();                                                           \
        gpa += 1024; gpb += 1024;                                              \
    }

    for (int i = 0; i < NKCH; i += 3) {
        GEMM_BODY(i,     0, 2)
        GEMM_BODY(i + 1, 1, 0)
        GEMM_BODY(i + 2, 2, 1)
    }
#undef GEMM_BODY
#undef MMAS
#undef PF
#undef LOADFRAG

    const int warpM = (wid >> 1) * 64;
    const int warpN = (wid & 1) * 64;
    const int n0 = bx * 128;
    const float* bp = bias + (size_t)e * NDIM + n0 + warpN;

    float2 br[8];
#pragma unroll
    for (int nf = 0; nf < 8; nf++)
        br[nf] = *(const float2*)(bp + nf * 8 + tig * 2);

    if (EPI_FRAG) {
        __syncthreads();
        const int tw = lid ^ (((lid >> 3) & 3) << 1);
        __half2* sh = (__half2*)smem + (wid & 1) * 4096 + (wid >> 1) * 2048 + tw * 4;
#pragma unroll
        for (int mf = 0; mf < 4; mf++) {
#pragma unroll
            for (int nf = 0; nf < 8; nf++) {
                float v0 = gelu_exact(acc[mf][nf][0] + br[nf].x);
                float v1 = gelu_exact(acc[mf][nf][1] + br[nf].y);
                float v2 = gelu_exact(acc[mf][nf][2] + br[nf].x);
                float v3 = gelu_exact(acc[mf][nf][3] + br[nf].y);
                __half2 h0 = __floats2half2_rn(v0, v1);
                __half2 h1 = __floats2half2_rn(v2, v3);
                uint2 u;
                u.x = *(uint32_t*)&h0;
                u.y = *(uint32_t*)&h1;
                *(uint2*)(sh + mf * 512 + (nf >> 1) * 128 + 2 * (nf & 1)) = u;
            }
        }
        __syncthreads();
        float4* dst = (float4*)((__half*)Cout +
            (((size_t)((e * MTILES + blockIdx.y) * KCH2 + bx * 2)) << 13));
        const float4* st = (const float4*)smem;
#pragma unroll
        for (int u = tid; u < 2048; u += 128) {
            int t = u & 31;
            int twc = t ^ (((t >> 3) & 3) << 1);
            dst[u] = st[(u & ~31) | twc];
        }
    } else {
        float* Cf = (float*)Cout;
#pragma unroll
        for (int mf = 0; mf < 4; mf++)
#pragma unroll
            for (int half = 0; half < 2; half++) {
                int m = m0 + warpM + mf * 16 + gid + half * 8;
                if (m >= Me) continue;
                float* Crow = Cf + (size_t)(e * CAP + m) * NDIM + n0 + warpN + tig * 2;
#pragma unroll
                for (int nf = 0; nf < 8; nf++) {
                    float2 o;
                    o.x = acc[mf][nf][half * 2 + 0] + br[nf].x;
                    o.y = acc[mf][nf][half * 2 + 1] + br[nf].y;
                    *(float2*)(Crow + nf * 8) = o;
                }
            }
    }
}

// ---------------------------------------------------------------------------
// combine + LayerNorm
// ---------------------------------------------------------------------------
__global__ __launch_bounds__(256) void combine_ln_kernel(
    const float* __restrict__ lnw,
    const float* __restrict__ lnb,
    float* __restrict__ out)
{
    const int t   = blockIdx.x;
    const int tid = threadIdx.x;
    const int s0  = g_slot[2 * t + 0];
    const int s1  = g_slot[2 * t + 1];
    const float w0 = g_route_w[2 * t + 0];
    const float w1 = g_route_w[2 * t + 1];

    float v[3];
    float sum = 0.f;
#pragma unroll
    for (int r = 0; r < 3; r++) {
        int i = r * 256 + tid;
        float a = (s0 >= 0) ? g_Y[(size_t)s0 * DIM + i] : 0.f;
        float b = (s1 >= 0) ? g_Y[(size_t)s1 * DIM + i] : 0.f;
        v[r] = w0 * a + w1 * b;
        sum += v[r];
    }

    __shared__ float red[256];
    red[tid] = sum;
    __syncthreads();
#pragma unroll
    for (int o = 128; o > 0; o >>= 1) {
        if (tid < o) red[tid] += red[tid + o];
        __syncthreads();
    }
    float mu = red[0] * (1.f / (float)DIM);
    __syncthreads();

    float sq = 0.f;
#pragma unroll
    for (int r = 0; r < 3; r++) { float d = v[r] - mu; sq += d * d; }
    red[tid] = sq;
    __syncthreads();
#pragma unroll
    for (int o = 128; o > 0; o >>= 1) {
        if (tid < o) red[tid] += red[tid + o];
        __syncthreads();
    }
    float rstd = rsqrtf(red[0] * (1.f / (float)DIM) + 1e-5f);

#pragma unroll
    for (int r = 0; r < 3; r++) {
        int i = r * 256 + tid;
        out[(size_t)t * DIM + i] = (v[r] - mu) * rstd * lnw[i] + lnb[i];
    }
}

// ---------------------------------------------------------------------------
// Launch:  prep(0), assign(1), gather(2), gemm1(3), gemm2(4), combine(5)
// ---------------------------------------------------------------------------
extern "C" void kernel_launch(void* const* d_in, const int* in_sizes, int n_in,
                              void* d_out, int out_size)
{
    const float* x   = (const float*)d_in[0];
    const float* wg  = (const float*)d_in[1];
    const float* w1  = (const float*)d_in[2];
    const float* b1  = (const float*)d_in[3];
    const float* w2  = (const float*)d_in[4];
    const float* b2  = (const float*)d_in[5];
    const float* lnw = (const float*)d_in[6];
    const float* lnb = (const float*)d_in[7];
    float* out = (float*)d_out;

    const int SMEM_BYTES = 3 * 8192 * 4;   // 98304
    cudaFuncSetAttribute(gemm_f16_kernel<KCH1, HID, true>,
                         cudaFuncAttributeMaxDynamicSharedMemorySize, SMEM_BYTES);
    cudaFuncSetAttribute(gemm_f16_kernel<KCH2, DIM, false>,
                         cudaFuncAttributeMaxDynamicSharedMemorySize, SMEM_BYTES);

    __half* w1f; cudaGetSymbolAddress((void**)&w1f, g_w1f);
    __half* w2f; cudaGetSymbolAddress((void**)&w2f, g_w2f);
    __half* xg;  cudaGetSymbolAddress((void**)&xg,  g_xg);
    __half* Hbuf; cudaGetSymbolAddress((void**)&Hbuf, g_H);
    float* Ybuf; cudaGetSymbolAddress((void**)&Ybuf, g_Y);

    prep_kernel<<<4096 + 4608, 256>>>(x, wg, w1, w2);
    assign_kernel<<<N_TOK / 256, 256>>>();
    gather_frag_kernel<<<dim3(CAP / 16, NEXP), 256>>>(x);

    gemm_f16_kernel<KCH1, HID, true><<<dim3(HID / 128, MTILES, NEXP), 128, SMEM_BYTES>>>(
        xg, w1f, b1, Hbuf);
    gemm_f16_kernel<KCH2, DIM, false><<<dim3(DIM / 128, MTILES, NEXP), 128, SMEM_BYTES>>>(
        Hbuf, w2f, b2, Ybuf);

    combine_ln_kernel<<<N_TOK, 256>>>(lnw, lnb, out);
}

// round 17
// speedup vs baseline: 1.0754x; 1.0248x over previous
#include <cuda_runtime.h>
#include <cuda_fp16.h>
#include <math.h>
#include <stdint.h>

#define N_TOK 32768
#define DIM   768
#define HID   3072
#define NEXP  8
#define CAP   10240
#define MTILES (CAP / 128)          // 80
#define KCH1  (DIM / 64)            // 12
#define KCH2  (HID / 64)            // 48

// ---------------------------------------------------------------------------
// Scratch. Fragment-major fp16 blobs, 16KB each (1024 float4 units).
// ---------------------------------------------------------------------------
__device__ int    g_cnt[NEXP];
__device__ float  g_route_w[N_TOK * 2];
__device__ int    g_tokidx[NEXP * CAP];
__device__ int    g_slot[N_TOK * 2];
__device__ __half g_xg [(size_t)NEXP * CAP * DIM];
__device__ __half g_w1f[(size_t)NEXP * DIM * HID];
__device__ __half g_w2f[(size_t)NEXP * HID * DIM];
__device__ __half g_H  [(size_t)NEXP * CAP * HID];
__device__ float  g_Y  [(size_t)NEXP * CAP * DIM];

// ---------------------------------------------------------------------------
// Helpers
// ---------------------------------------------------------------------------
__device__ __forceinline__ void cp16s(uint32_t dst, const void* src) {
    asm volatile("cp.async.cg.shared.global [%0], [%1], 16;" :: "r"(dst), "l"(src));
}
#define CP_COMMIT() asm volatile("cp.async.commit_group;" ::: "memory")
#define CP_WAIT1()  asm volatile("cp.async.wait_group 1;" ::: "memory")

#define MMA_F16(c, a, b) \
    asm volatile("mma.sync.aligned.m16n8k16.row.col.f32.f16.f16.f32 " \
        "{%0,%1,%2,%3}, {%4,%5,%6,%7}, {%8,%9}, {%0,%1,%2,%3};" \
        : "+f"((c)[0]), "+f"((c)[1]), "+f"((c)[2]), "+f"((c)[3]) \
        : "r"((a)[0]), "r"((a)[1]), "r"((a)[2]), "r"((a)[3]), \
          "r"((b)[0]), "r"((b)[1]))

__device__ __forceinline__ float gelu_exact(float v) {
    return 0.5f * v * (1.f + erff(v * 0.70710678118654752f));
}

// ---------------------------------------------------------------------------
// Kernel 0: zero counters (must precede prep: router tail does atomicAdd)
// ---------------------------------------------------------------------------
__global__ void zero_counts_kernel() {
    if (threadIdx.x < NEXP) g_cnt[threadIdx.x] = 0;
}

// ---------------------------------------------------------------------------
// Kernel 1: PREP = router (+ slot assignment fused) + weight->blob transforms.
//   blocks [0, 4096):      router, 8 tokens per block (1 warp/token),
//                          lane 0 assigns slots via atomicAdd.
//   blocks [4096, 8704):   w1/w2 -> fp16 blob transforms.
// ---------------------------------------------------------------------------
__global__ __launch_bounds__(256) void prep_kernel(
    const float* __restrict__ x,  const float* __restrict__ wg,
    const float* __restrict__ w1, const float* __restrict__ w2)
{
    __shared__ float tile[64][132];
    const int b = blockIdx.x;
    const int tid = threadIdx.x;

    if (b < 4096) {
        int warp = b * 8 + (tid >> 5);
        int lane = tid & 31;
        const float* xr = x + (size_t)warp * DIM;

        float acc[NEXP];
#pragma unroll
        for (int e = 0; e < NEXP; e++) acc[e] = 0.f;
        for (int j = lane; j < DIM; j += 32) {
            float xv = xr[j];
            const float* wr = wg + j * NEXP;
#pragma unroll
            for (int e = 0; e < NEXP; e++) acc[e] += xv * wr[e];
        }
#pragma unroll
        for (int e = 0; e < NEXP; e++) {
#pragma unroll
            for (int o = 16; o > 0; o >>= 1)
                acc[e] += __shfl_xor_sync(0xffffffffu, acc[e], o);
        }
        if (lane == 0) {
            int e0 = 0; float v0 = acc[0];
#pragma unroll
            for (int e = 1; e < NEXP; e++) if (acc[e] > v0) { v0 = acc[e]; e0 = e; }
            int e1 = -1; float v1 = -3.4e38f;
#pragma unroll
            for (int e = 0; e < NEXP; e++) if (e != e0 && acc[e] > v1) { v1 = acc[e]; e1 = e; }
            float ex = expf(v1 - v0);
            float s  = 1.f + ex;
            g_route_w[2 * warp + 0] = 1.f / s;
            g_route_w[2 * warp + 1] = ex / s;
            int p0 = atomicAdd(&g_cnt[e0], 1);
            if (p0 < CAP) { g_tokidx[e0 * CAP + p0] = warp; g_slot[2 * warp + 0] = e0 * CAP + p0; }
            else          { g_slot[2 * warp + 0] = -1; }
            int p1 = atomicAdd(&g_cnt[e1], 1);
            if (p1 < CAP) { g_tokidx[e1 * CAP + p1] = warp; g_slot[2 * warp + 1] = e1 * CAP + p1; }
            else          { g_slot[2 * warp + 1] = -1; }
        }
        return;
    }

    int wb = b - 4096;
    const float* w;
    __half* out;
    int KD, nkc;
    size_t ndiv;
    if (wb < 2304) { w = w1; out = g_w1f; KD = DIM; nkc = 12; ndiv = HID / 128; }
    else           { wb -= 2304; w = w2; out = g_w2f; KD = HID; nkc = 48; ndiv = DIM / 128; }
    const int ND = (int)(ndiv * 128);
    const int e  = wb / 288;
    const int r  = wb % 288;
    const int nt = r / nkc;
    const int kc = r % nkc;

    const float* src = w + ((size_t)e * KD + kc * 64) * ND + nt * 128;
#pragma unroll
    for (int u = tid; u < 2048; u += 256) {
        int rr = u >> 5, c = (u & 31) * 4;
        float4 v = *(const float4*)(src + (size_t)rr * ND + c);
        tile[rr][c + 0] = v.x; tile[rr][c + 1] = v.y;
        tile[rr][c + 2] = v.z; tile[rr][c + 3] = v.w;
    }
    __syncthreads();

    float4* dst = (float4*)(out + (((size_t)(e * ndiv + nt) * nkc + kc) << 13));
#pragma unroll
    for (int u = tid; u < 1024; u += 256) {
        int t = u & 31, pp = (u >> 5) & 7, ks = u >> 8;
        int gid = t >> 2, tig = t & 3;
        __half2 h[4];
#pragma unroll
        for (int j = 0; j < 4; j++) {
            int n = pp * 16 + 8 * (j >> 1) + gid;
            int k = ks * 16 + tig * 2 + 8 * (j & 1);
            h[j] = __floats2half2_rn(tile[k][n], tile[k + 1][n]);
        }
        float4 v;
        v.x = __uint_as_float(*(uint32_t*)&h[0]);
        v.y = __uint_as_float(*(uint32_t*)&h[1]);
        v.z = __uint_as_float(*(uint32_t*)&h[2]);
        v.w = __uint_as_float(*(uint32_t*)&h[3]);
        dst[u] = v;
    }
}

// ---------------------------------------------------------------------------
// Kernel 2: gather routed tokens into fp16 A-blobs
// ---------------------------------------------------------------------------
__global__ __launch_bounds__(256) void gather_frag_kernel(const float* __restrict__ x) {
    const int e = blockIdx.y;
    const int Me = min(g_cnt[e], CAP);
    const int g16 = blockIdx.x;
    const int base = g16 * 16;
    if (base >= Me) return;

    __shared__ float rows[16][772];
    const int tid = threadIdx.x;

    for (int u = tid; u < 16 * 192; u += 256) {
        int r = u / 192, c = (u % 192) * 4;
        int pos = base + r;
        if (pos < Me) {
            int tok = g_tokidx[e * CAP + pos];
            float4 v = *(const float4*)(x + (size_t)tok * DIM + c);
            rows[r][c + 0] = v.x; rows[r][c + 1] = v.y;
            rows[r][c + 2] = v.z; rows[r][c + 3] = v.w;
        } else {
            rows[r][c + 0] = 0.f; rows[r][c + 1] = 0.f;
            rows[r][c + 2] = 0.f; rows[r][c + 3] = 0.f;
        }
    }
    __syncthreads();

    const int mtile = g16 >> 3, m16blk = g16 & 7;
    float4* outb = (float4*)g_xg;
    for (int u = tid; u < 1536; u += 256) {
        int kc = u >> 7, r = u & 127;
        int ks = r >> 5, t = r & 31;
        int gid = t >> 2, tig = t & 3;
        __half2 h[4];
#pragma unroll
        for (int j = 0; j < 4; j++) {
            int row = gid + 8 * (j & 1);
            int col = kc * 64 + ks * 16 + tig * 2 + 8 * (j >> 1);
            h[j] = __floats2half2_rn(rows[row][col], rows[row][col + 1]);
        }
        float4 v;
        v.x = __uint_as_float(*(uint32_t*)&h[0]);
        v.y = __uint_as_float(*(uint32_t*)&h[1]);
        v.z = __uint_as_float(*(uint32_t*)&h[2]);
        v.w = __uint_as_float(*(uint32_t*)&h[3]);
        outb[(((size_t)((e * MTILES + mtile) * KCH1 + kc)) << 10) + m16blk * 128 + ks * 32 + t] = v;
    }
}

// ---------------------------------------------------------------------------
// fp16 fragment-major GEMM. CTA 128x128, 4 warps (2x2), warp tile 64x64.
//   R16 mainloop (3-stage ring, interleaved prefetch, frag double-buffer).
//   R17: gemm1 epilogue writes H blobs DIRECTLY to global via coalesced
//   STG.128 (raw t=lid layout) — no smem staging, no extra barriers.
// ---------------------------------------------------------------------------
template<int NKCH, int NDIM, bool EPI_FRAG>
__global__ __launch_bounds__(128, 2) void gemm_f16_kernel(
    const __half* __restrict__ Ablobs,
    const __half* __restrict__ Bblobs,
    const float* __restrict__ bias,
    void* __restrict__ Cout)
{
    static_assert(NKCH % 3 == 0, "stage ring requires NKCH % 3 == 0");
    const int e  = blockIdx.z;
    const int Me = min(g_cnt[e], CAP);
    const int m0 = blockIdx.y * 128;
    if (m0 >= Me) return;
    const int bx = blockIdx.x;

    extern __shared__ float smem[];           // 3 stages x 8192 floats (32KB)
    const int tid = threadIdx.x;
    const int wid = tid >> 5, lid = tid & 31;
    const int gid = lid >> 2, tig = lid & 3;
    const int wMblk = (wid >> 1) * 4;
    const int pbase = (wid & 1) * 4;

    const float4* Ab = (const float4*)(Ablobs + (((size_t)(e * MTILES + blockIdx.y) * NKCH) << 13));
    const float4* Bb = (const float4*)(Bblobs + (((size_t)(e * (NDIM / 128) + bx) * NKCH) << 13));

    uint32_t cpd;
    asm("{ .reg .u64 t; cvta.to.shared.u64 t, %1; cvt.u32.u64 %0, t; }"
        : "=r"(cpd) : "l"(smem));
    cpd += tid * 16;

    const float4* fA = (const float4*)smem + wMblk * 128 + lid;
    const float4* fB = (const float4*)smem + 1024 + pbase * 32 + lid;

    float acc[4][8][4];
#pragma unroll
    for (int mf = 0; mf < 4; mf++)
#pragma unroll
        for (int nf = 0; nf < 8; nf++)
#pragma unroll
            for (int q = 0; q < 4; q++) acc[mf][nf][q] = 0.f;

    // prologue: full issue of chunks 0 and 1 (16 f4 per thread per chunk)
    {
        const float4* a0 = Ab + tid;
        const float4* b0 = Bb + tid;
#pragma unroll
        for (int s = 0; s < 2; s++) {
#pragma unroll
            for (int j = 0; j < 8; j++)
                cp16s(cpd + s * 32768 + j * 2048, a0 + s * 1024 + j * 128);
#pragma unroll
            for (int j = 0; j < 8; j++)
                cp16s(cpd + s * 32768 + 16384 + j * 2048, b0 + s * 1024 + j * 128);
            CP_COMMIT();
        }
    }

    const float4* gpa = Ab + 2048 + tid;
    const float4* gpb = Bb + 2048 + tid;

    uint32_t a[2][4][4], b[2][8][2];

#define LOADFRAG(S_CUR, KS, BUF)                                               \
    {                                                                          \
        _Pragma("unroll")                                                      \
        for (int mf = 0; mf < 4; mf++) {                                       \
            float4 v = fA[(S_CUR) * 2048 + mf * 128 + (KS) * 32];              \
            a[BUF][mf][0] = __float_as_uint(v.x);                              \
            a[BUF][mf][1] = __float_as_uint(v.y);                              \
            a[BUF][mf][2] = __float_as_uint(v.z);                              \
            a[BUF][mf][3] = __float_as_uint(v.w);                              \
        }                                                                      \
        _Pragma("unroll")                                                      \
        for (int q = 0; q < 4; q++) {                                          \
            float4 v = fB[(S_CUR) * 2048 + (KS) * 256 + q * 32];               \
            b[BUF][2 * q + 0][0] = __float_as_uint(v.x);                       \
            b[BUF][2 * q + 0][1] = __float_as_uint(v.y);                       \
            b[BUF][2 * q + 1][0] = __float_as_uint(v.z);                       \
            b[BUF][2 * q + 1][1] = __float_as_uint(v.w);                       \
        }                                                                      \
    }

#define PF(KS, S_PF)                                                           \
    if (pf) {                                                                  \
        _Pragma("unroll")                                                      \
        for (int jj = 0; jj < 4; jj++) {                                       \
            int j = (KS) * 4 + jj;                                             \
            if (j < 8) cp16s(cpd + (S_PF) * 32768 + j * 2048, gpa + j * 128);  \
            else       cp16s(cpd + (S_PF) * 32768 + 16384 + (j - 8) * 2048,    \
                             gpb + (j - 8) * 128);                             \
        }                                                                      \
    }

#define MMAS(BUF)                                                              \
    _Pragma("unroll")                                                          \
    for (int mf = 0; mf < 4; mf++)                                             \
        _Pragma("unroll")                                                      \
        for (int nf = 0; nf < 8; nf++)                                         \
            MMA_F16(acc[mf][nf], a[BUF][mf], b[BUF][nf]);

#define GEMM_BODY(ICHUNK, S_CUR, S_PF)                                         \
    {                                                                          \
        const bool pf = ((ICHUNK) + 2 < NKCH);                                 \
        CP_WAIT1();                                                            \
        __syncthreads();                                                       \
        LOADFRAG(S_CUR, 0, 0)                                                  \
        LOADFRAG(S_CUR, 1, 1) PF(0, S_PF) MMAS(0)                              \
        LOADFRAG(S_CUR, 2, 0) PF(1, S_PF) MMAS(1)                              \
        LOADFRAG(S_CUR, 3, 1) PF(2, S_PF) MMAS(0)                              \
                              PF(3, S_PF) MMAS(1)                              \
        CP_COMMIT();                                                           \
        gpa += 1024; gpb += 1024;                                              \
    }

    for (int i = 0; i < NKCH; i += 3) {
        GEMM_BODY(i,     0, 2)
        GEMM_BODY(i + 1, 1, 0)
        GEMM_BODY(i + 2, 2, 1)
    }
#undef GEMM_BODY
#undef MMAS
#undef PF
#undef LOADFRAG

    const int warpM = (wid >> 1) * 64;
    const int warpN = (wid & 1) * 64;
    const int n0 = bx * 128;
    const float* bp = bias + (size_t)e * NDIM + n0 + warpN;

    float2 br[8];
#pragma unroll
    for (int nf = 0; nf < 8; nf++)
        br[nf] = *(const float2*)(bp + nf * 8 + tig * 2);

    if (EPI_FRAG) {
        // Direct coalesced H-blob stores (global layout uses raw t = lid):
        //   float4 unit = Hb4 + (wid&1)*1024 + (((wid>>1)*4+mf)*4 + ks)*32 + lid
        //   uint4 words: j0=(half0,nf=2ks) j1=(half1,2ks) j2=(half0,2ks+1) j3=(half1,2ks+1)
        float4* Hb4 = (float4*)((__half*)Cout +
            (((size_t)((e * MTILES + blockIdx.y) * KCH2 + bx * 2)) << 13))
            + (wid & 1) * 1024 + (wid >> 1) * 512 + lid;
#pragma unroll
        for (int mf = 0; mf < 4; mf++) {
#pragma unroll
            for (int ks = 0; ks < 4; ks++) {
                const int nfa = 2 * ks, nfb = 2 * ks + 1;
                float v0 = gelu_exact(acc[mf][nfa][0] + br[nfa].x);
                float v1 = gelu_exact(acc[mf][nfa][1] + br[nfa].y);
                float v2 = gelu_exact(acc[mf][nfa][2] + br[nfa].x);
                float v3 = gelu_exact(acc[mf][nfa][3] + br[nfa].y);
                float v4 = gelu_exact(acc[mf][nfb][0] + br[nfb].x);
                float v5 = gelu_exact(acc[mf][nfb][1] + br[nfb].y);
                float v6 = gelu_exact(acc[mf][nfb][2] + br[nfb].x);
                float v7 = gelu_exact(acc[mf][nfb][3] + br[nfb].y);
                __half2 h0 = __floats2half2_rn(v0, v1);
                __half2 h1 = __floats2half2_rn(v2, v3);
                __half2 h2 = __floats2half2_rn(v4, v5);
                __half2 h3 = __floats2half2_rn(v6, v7);
                float4 o;
                o.x = __uint_as_float(*(uint32_t*)&h0);
                o.y = __uint_as_float(*(uint32_t*)&h1);
                o.z = __uint_as_float(*(uint32_t*)&h2);
                o.w = __uint_as_float(*(uint32_t*)&h3);
                Hb4[mf * 128 + ks * 32] = o;
            }
        }
    } else {
        float* Cf = (float*)Cout;
#pragma unroll
        for (int mf = 0; mf < 4; mf++)
#pragma unroll
            for (int half = 0; half < 2; half++) {
                int m = m0 + warpM + mf * 16 + gid + half * 8;
                if (m >= Me) continue;
                float* Crow = Cf + (size_t)(e * CAP + m) * NDIM + n0 + warpN + tig * 2;
#pragma unroll
                for (int nf = 0; nf < 8; nf++) {
                    float2 o;
                    o.x = acc[mf][nf][half * 2 + 0] + br[nf].x;
                    o.y = acc[mf][nf][half * 2 + 1] + br[nf].y;
                    *(float2*)(Crow + nf * 8) = o;
                }
            }
    }
}

// ---------------------------------------------------------------------------
// combine + LayerNorm
// ---------------------------------------------------------------------------
__global__ __launch_bounds__(256) void combine_ln_kernel(
    const float* __restrict__ lnw,
    const float* __restrict__ lnb,
    float* __restrict__ out)
{
    const int t   = blockIdx.x;
    const int tid = threadIdx.x;
    const int s0  = g_slot[2 * t + 0];
    const int s1  = g_slot[2 * t + 1];
    const float w0 = g_route_w[2 * t + 0];
    const float w1 = g_route_w[2 * t + 1];

    float v[3];
    float sum = 0.f;
#pragma unroll
    for (int r = 0; r < 3; r++) {
        int i = r * 256 + tid;
        float a = (s0 >= 0) ? g_Y[(size_t)s0 * DIM + i] : 0.f;
        float b = (s1 >= 0) ? g_Y[(size_t)s1 * DIM + i] : 0.f;
        v[r] = w0 * a + w1 * b;
        sum += v[r];
    }

    __shared__ float red[256];
    red[tid] = sum;
    __syncthreads();
#pragma unroll
    for (int o = 128; o > 0; o >>= 1) {
        if (tid < o) red[tid] += red[tid + o];
        __syncthreads();
    }
    float mu = red[0] * (1.f / (float)DIM);
    __syncthreads();

    float sq = 0.f;
#pragma unroll
    for (int r = 0; r < 3; r++) { float d = v[r] - mu; sq += d * d; }
    red[tid] = sq;
    __syncthreads();
#pragma unroll
    for (int o = 128; o > 0; o >>= 1) {
        if (tid < o) red[tid] += red[tid + o];
        __syncthreads();
    }
    float rstd = rsqrtf(red[0] * (1.f / (float)DIM) + 1e-5f);

#pragma unroll
    for (int r = 0; r < 3; r++) {
        int i = r * 256 + tid;
        out[(size_t)t * DIM + i] = (v[r] - mu) * rstd * lnw[i] + lnb[i];
    }
}

// ---------------------------------------------------------------------------
// Launch:  zero(0), prep(1), gather(2), gemm1(3), gemm2(4), combine(5)
// ---------------------------------------------------------------------------
extern "C" void kernel_launch(void* const* d_in, const int* in_sizes, int n_in,
                              void* d_out, int out_size)
{
    const float* x   = (const float*)d_in[0];
    const float* wg  = (const float*)d_in[1];
    const float* w1  = (const float*)d_in[2];
    const float* b1  = (const float*)d_in[3];
    const float* w2  = (const float*)d_in[4];
    const float* b2  = (const float*)d_in[5];
    const float* lnw = (const float*)d_in[6];
    const float* lnb = (const float*)d_in[7];
    float* out = (float*)d_out;

    const int SMEM_BYTES = 3 * 8192 * 4;   // 98304
    cudaFuncSetAttribute(gemm_f16_kernel<KCH1, HID, true>,
                         cudaFuncAttributeMaxDynamicSharedMemorySize, SMEM_BYTES);
    cudaFuncSetAttribute(gemm_f16_kernel<KCH2, DIM, false>,
                         cudaFuncAttributeMaxDynamicSharedMemorySize, SMEM_BYTES);

    __half* w1f; cudaGetSymbolAddress((void**)&w1f, g_w1f);
    __half* w2f; cudaGetSymbolAddress((void**)&w2f, g_w2f);
    __half* xg;  cudaGetSymbolAddress((void**)&xg,  g_xg);
    __half* Hbuf; cudaGetSymbolAddress((void**)&Hbuf, g_H);
    float* Ybuf; cudaGetSymbolAddress((void**)&Ybuf, g_Y);

    zero_counts_kernel<<<1, 32>>>();
    prep_kernel<<<4096 + 4608, 256>>>(x, wg, w1, w2);
    gather_frag_kernel<<<dim3(CAP / 16, NEXP), 256>>>(x);

    gemm_f16_kernel<KCH1, HID, true><<<dim3(HID / 128, MTILES, NEXP), 128, SMEM_BYTES>>>(
        xg, w1f, b1, Hbuf);
    gemm_f16_kernel<KCH2, DIM, false><<<dim3(DIM / 128, MTILES, NEXP), 128, SMEM_BYTES>>>(
        Hbuf, w2f, b2, Ybuf);

    combine_ln_kernel<<<N_TOK, 256>>>(lnw, lnb, out);
}